// round 8
// baseline (speedup 1.0000x reference)
#include <cuda_runtime.h>
#include <cuda_fp16.h>
#include <cstdint>

// Problem constants (fixed by the dataset)
#define NCH   12
#define GD    160
#define GH    160
#define GW    160
#define GVOL  (GD * GH * GW)          // 4,096,000 voxels
#define VOXH  16                      // halfs per padded voxel (12 data + 4 pad) = 32 B
#define ZSPLIT 80                     // slab boundary

// Padded interleaved channel-last fp16 grid: [D*H*W, 16] halfs = 32 B/voxel,
// 131 MB. A corner pair (x0, x0+1) is 64 contiguous, 32B-aligned bytes ->
// 4x LDG.128. +4 pad voxels so the unconditional x0+1 read at the last voxel
// stays in bounds (weight fx == 0 there; padding is zero-initialized).
__device__ __align__(32) __half g_grid_h[((size_t)GVOL + 4) * VOXH];

// ---- cache-policy load/store helpers ---------------------------------------
__device__ __forceinline__ uint64_t evict_last_policy() {
    uint64_t pol;
    asm("createpolicy.fractional.L2::evict_last.b64 %0, 1.0;" : "=l"(pol));
    return pol;
}
__device__ __forceinline__ uint4 ldg_el_u4(const void* p, uint64_t pol) {
    uint4 v;
    asm("ld.global.nc.L2::cache_hint.v4.u32 {%0,%1,%2,%3}, [%4], %5;"
        : "=r"(v.x), "=r"(v.y), "=r"(v.z), "=r"(v.w) : "l"(p), "l"(pol));
    return v;
}
__device__ __forceinline__ void stg_el_u4(void* p, uint4 v, uint64_t pol) {
    asm volatile("st.global.L2::cache_hint.v4.u32 [%0], {%1,%2,%3,%4}, %5;"
                 :: "l"(p), "r"(v.x), "r"(v.y), "r"(v.z), "r"(v.w), "l"(pol) : "memory");
}

// ---------------------------------------------------------------------------
// Pass 1: transpose+convert [C, D, H, W] fp32 -> padded channel-last fp16.
// fp32 reads stream (evict-first); fp16 writes 2x STG.128 per voxel.
// ---------------------------------------------------------------------------
__global__ void __launch_bounds__(256) convert_cl_kernel(const float* __restrict__ grid) {
    int v = blockIdx.x * blockDim.x + threadIdx.x;
    if (v >= GVOL) return;

    uint64_t pol = evict_last_policy();

    __half h[VOXH];
#pragma unroll
    for (int c = 0; c < NCH; c++)
        h[c] = __float2half(__ldcs(grid + (size_t)c * GVOL + v));
#pragma unroll
    for (int c = NCH; c < VOXH; c++)
        h[c] = __half(0.0f);

    char* dst = reinterpret_cast<char*>(g_grid_h) + (size_t)v * 32;
    const uint4* s = reinterpret_cast<const uint4*>(h);
    stg_el_u4(dst,      s[0], pol);
    stg_el_u4(dst + 16, s[1], pol);
}

// ---------------------------------------------------------------------------
// Pass 2a/2b: trilinear sample, one thread per point, z-slab restricted so
// the ~66 MB slab stays L2-resident. 16x LDG.128 gathers per point.
// ---------------------------------------------------------------------------
__device__ __forceinline__ float2 u2f2(unsigned u) {
    __half2 h = *reinterpret_cast<__half2*>(&u);
    return __half22float2(h);
}

__global__ void __launch_bounds__(256, 4) trilinear_sample_kernel(
    const float* __restrict__ xyz,
    const float* __restrict__ xyz_min,
    const float* __restrict__ xyz_max,
    float* __restrict__ out,
    int n, int z_lo, int z_hi)
{
    int i = blockIdx.x * blockDim.x + threadIdx.x;
    if (i >= n) return;

    float p0 = __ldcs(xyz + 3 * (size_t)i + 0);
    float p1 = __ldcs(xyz + 3 * (size_t)i + 1);
    float p2 = __ldcs(xyz + 3 * (size_t)i + 2);

    float mn0 = __ldg(xyz_min + 0), mn1 = __ldg(xyz_min + 1), mn2 = __ldg(xyz_min + 2);
    float mx0 = __ldg(xyz_max + 0), mx1 = __ldg(xyz_max + 1), mx2 = __ldg(xyz_max + 2);

    float u0 = (p0 - mn0) / (mx0 - mn0);
    float u1 = (p1 - mn1) / (mx1 - mn1);
    float u2 = (p2 - mn2) / (mx2 - mn2);

    // px indexes W (from u2), py indexes H (from u1), pz indexes D (from u0)
    float px = u2 * (float)(GW - 1);
    float py = u1 * (float)(GH - 1);
    float pz = u0 * (float)(GD - 1);

    float xf = floorf(px), yf = floorf(py), zf = floorf(pz);

    int z0 = min(max((int)zf, 0), GD - 1);
    if (z0 < z_lo || z0 >= z_hi) return;   // other slab's pass handles it

    float fx = px - xf, fy = py - yf, fz = pz - zf;

    int x0 = min(max((int)xf, 0), GW - 1);
    int y0 = min(max((int)yf, 0), GH - 1);
    int y1 = min(y0 + 1, GH - 1);
    int z1 = min(z0 + 1, GD - 1);

    float wx0 = 1.0f - fx, wx1 = fx;
    float wy0 = 1.0f - fy, wy1 = fy;
    float wz0 = 1.0f - fz, wz1 = fz;

    float wp[4];
    wp[0] = wz0 * wy0;
    wp[1] = wz0 * wy1;
    wp[2] = wz1 * wy0;
    wp[3] = wz1 * wy1;

    const char* gbase = reinterpret_cast<const char*>(g_grid_h);
    const char* vp[4];
    vp[0] = gbase + (size_t)((z0 * GH + y0) * GW + x0) * 32;
    vp[1] = gbase + (size_t)((z0 * GH + y1) * GW + x0) * 32;
    vp[2] = gbase + (size_t)((z1 * GH + y0) * GW + x0) * 32;
    vp[3] = gbase + (size_t)((z1 * GH + y1) * GW + x0) * 32;

    uint64_t pol = evict_last_policy();

    float acc[NCH];
#pragma unroll
    for (int c = 0; c < NCH; c++) acc[c] = 0.0f;

    // Process pairs two at a time: 8x LDG.128 in flight, then FMA.
#pragma unroll
    for (int pb = 0; pb < 4; pb += 2) {
        uint4 Q[8];
#pragma unroll
        for (int t = 0; t < 2; t++) {
#pragma unroll
            for (int k = 0; k < 4; k++)
                Q[t * 4 + k] = ldg_el_u4(vp[pb + t] + 16 * k, pol);
        }

#pragma unroll
        for (int t = 0; t < 2; t++) {
            int p = pb + t;
            float w0 = wp[p] * wx0;
            float w1 = wp[p] * wx1;
            uint4 q0 = Q[t * 4 + 0];   // x0   ch0-7
            uint4 q1 = Q[t * 4 + 1];   // x0   ch8-11 (+pad)
            uint4 q2 = Q[t * 4 + 2];   // x0+1 ch0-7
            uint4 q3 = Q[t * 4 + 3];   // x0+1 ch8-11 (+pad)

            float2 a, b;
            a = u2f2(q0.x); b = u2f2(q2.x);
            acc[0]  = fmaf(w0, a.x, fmaf(w1, b.x, acc[0]));
            acc[1]  = fmaf(w0, a.y, fmaf(w1, b.y, acc[1]));
            a = u2f2(q0.y); b = u2f2(q2.y);
            acc[2]  = fmaf(w0, a.x, fmaf(w1, b.x, acc[2]));
            acc[3]  = fmaf(w0, a.y, fmaf(w1, b.y, acc[3]));
            a = u2f2(q0.z); b = u2f2(q2.z);
            acc[4]  = fmaf(w0, a.x, fmaf(w1, b.x, acc[4]));
            acc[5]  = fmaf(w0, a.y, fmaf(w1, b.y, acc[5]));
            a = u2f2(q0.w); b = u2f2(q2.w);
            acc[6]  = fmaf(w0, a.x, fmaf(w1, b.x, acc[6]));
            acc[7]  = fmaf(w0, a.y, fmaf(w1, b.y, acc[7]));
            a = u2f2(q1.x); b = u2f2(q3.x);
            acc[8]  = fmaf(w0, a.x, fmaf(w1, b.x, acc[8]));
            acc[9]  = fmaf(w0, a.y, fmaf(w1, b.y, acc[9]));
            a = u2f2(q1.y); b = u2f2(q3.y);
            acc[10] = fmaf(w0, a.x, fmaf(w1, b.x, acc[10]));
            acc[11] = fmaf(w0, a.y, fmaf(w1, b.y, acc[11]));
        }
    }

    // out is [N, 12] row-major; 48B per thread -> 3x float4 streaming stores
    float4* o = reinterpret_cast<float4*>(out + (size_t)i * NCH);
    __stcs(o + 0, make_float4(acc[0], acc[1], acc[2],  acc[3]));
    __stcs(o + 1, make_float4(acc[4], acc[5], acc[6],  acc[7]));
    __stcs(o + 2, make_float4(acc[8], acc[9], acc[10], acc[11]));
}

extern "C" void kernel_launch(void* const* d_in, const int* in_sizes, int n_in,
                              void* d_out, int out_size) {
    const float* xyz     = (const float*)d_in[0];  // [N, 3]
    const float* grid    = (const float*)d_in[1];  // [1, 12, 160, 160, 160]
    const float* xyz_min = (const float*)d_in[2];  // [3]
    const float* xyz_max = (const float*)d_in[3];  // [3]
    float* out = (float*)d_out;                    // [N, 12]

    int n = in_sizes[0] / 3;

    {
        int threads = 256;
        int blocks = (GVOL + threads - 1) / threads;
        convert_cl_kernel<<<blocks, threads>>>(grid);
    }
    {
        int threads = 256;
        int blocks = (n + threads - 1) / threads;
        // Pass 0: lower z slab (grid z in [0, 80] incl. z1 overlap -> ~66 MB, L2-resident)
        trilinear_sample_kernel<<<blocks, threads>>>(xyz, xyz_min, xyz_max, out, n, 0, ZSPLIT);
        // Pass 1: upper z slab
        trilinear_sample_kernel<<<blocks, threads>>>(xyz, xyz_min, xyz_max, out, n, ZSPLIT, GD);
    }
}

// round 9
// speedup vs baseline: 1.1641x; 1.1641x over previous
#include <cuda_runtime.h>
#include <cuda_fp16.h>
#include <cstdint>

// Problem constants (fixed by the dataset)
#define NCH   12
#define GD    160
#define GH    160
#define GW    160
#define GVOL  (GD * GH * GW)          // 4,096,000 voxels

// Interleaved channel-last fp16 grid: [D*H*W, 12] halfs = 24 B/voxel, 98.3 MB.
// +pad voxels so the unconditional (x0+1) read at the last voxel stays in
// bounds (weight fx == 0 there; padding is zero-initialized).
__device__ __align__(16) __half g_grid_h[((size_t)GVOL + 4) * NCH];

// ---------------------------------------------------------------------------
// Pass 1: transpose+convert [C, D, H, W] fp32 -> [D*H*W, C] fp16.
// One thread = TWO consecutive voxels: 12x coalesced LDG.64 (float2) reads,
// 48 contiguous bytes out = 3x STG.128. fp32 reads stream (evict-first).
// ---------------------------------------------------------------------------
__global__ void __launch_bounds__(256) convert_cl_kernel(const float* __restrict__ grid) {
    int t = blockIdx.x * blockDim.x + threadIdx.x;
    int v = t * 2;                       // first of the two voxels
    if (v >= GVOL) return;

    __half h[2 * NCH];                   // interleaved: voxel v then v+1
#pragma unroll
    for (int c = 0; c < NCH; c++) {
        float2 f = __ldcs(reinterpret_cast<const float2*>(grid + (size_t)c * GVOL + v));
        h[c]       = __float2half(f.x);
        h[NCH + c] = __float2half(f.y);
    }

    uint4* dst = reinterpret_cast<uint4*>(g_grid_h + (size_t)v * NCH); // 48B aligned to 16
    const uint4* s = reinterpret_cast<const uint4*>(h);
    dst[0] = s[0];
    dst[1] = s[1];
    dst[2] = s[2];
}

// ---------------------------------------------------------------------------
// Pass 2: trilinear sample, one thread per point, all 12 channels.
// 24x LDG.64 gathers per point (4 corner-pairs x 48 contiguous bytes).
// 5 CTAs/SM (62.5% occ) for SM-wide miss concurrency.
// ---------------------------------------------------------------------------
__device__ __forceinline__ float2 u2f2(unsigned u) {
    __half2 h = *reinterpret_cast<__half2*>(&u);
    return __half22float2(h);
}

__global__ void __launch_bounds__(256, 5) trilinear_sample_kernel(
    const float* __restrict__ xyz,
    const float* __restrict__ xyz_min,
    const float* __restrict__ xyz_max,
    float* __restrict__ out,
    int n)
{
    int i = blockIdx.x * blockDim.x + threadIdx.x;
    if (i >= n) return;

    float p0 = __ldcs(xyz + 3 * (size_t)i + 0);
    float p1 = __ldcs(xyz + 3 * (size_t)i + 1);
    float p2 = __ldcs(xyz + 3 * (size_t)i + 2);

    float mn0 = __ldg(xyz_min + 0), mn1 = __ldg(xyz_min + 1), mn2 = __ldg(xyz_min + 2);
    float mx0 = __ldg(xyz_max + 0), mx1 = __ldg(xyz_max + 1), mx2 = __ldg(xyz_max + 2);

    float u0 = (p0 - mn0) / (mx0 - mn0);
    float u1 = (p1 - mn1) / (mx1 - mn1);
    float u2 = (p2 - mn2) / (mx2 - mn2);

    // px indexes W (from u2), py indexes H (from u1), pz indexes D (from u0)
    float px = u2 * (float)(GW - 1);
    float py = u1 * (float)(GH - 1);
    float pz = u0 * (float)(GD - 1);

    float xf = floorf(px), yf = floorf(py), zf = floorf(pz);
    float fx = px - xf,    fy = py - yf,    fz = pz - zf;

    int x0 = min(max((int)xf, 0), GW - 1);
    int y0 = min(max((int)yf, 0), GH - 1);
    int z0 = min(max((int)zf, 0), GD - 1);
    int y1 = min(y0 + 1, GH - 1);
    int z1 = min(z0 + 1, GD - 1);

    float wx0 = 1.0f - fx, wx1 = fx;
    float wy0 = 1.0f - fy, wy1 = fy;
    float wz0 = 1.0f - fz, wz1 = fz;

    float wp[4];
    wp[0] = wz0 * wy0;
    wp[1] = wz0 * wy1;
    wp[2] = wz1 * wy0;
    wp[3] = wz1 * wy1;

    int vidx[4];
    vidx[0] = (z0 * GH + y0) * GW + x0;
    vidx[1] = (z0 * GH + y1) * GW + x0;
    vidx[2] = (z1 * GH + y0) * GW + x0;
    vidx[3] = (z1 * GH + y1) * GW + x0;

    float acc[NCH];
#pragma unroll
    for (int c = 0; c < NCH; c++) acc[c] = 0.0f;

#pragma unroll
    for (int p = 0; p < 4; p++) {
        const uint2* vpp = reinterpret_cast<const uint2*>(g_grid_h + (size_t)vidx[p] * NCH);

        uint2 A0 = __ldg(vpp + 0);   // x0   ch0-3
        uint2 A1 = __ldg(vpp + 1);   // x0   ch4-7
        uint2 A2 = __ldg(vpp + 2);   // x0   ch8-11
        uint2 B0 = __ldg(vpp + 3);   // x0+1 ch0-3
        uint2 B1 = __ldg(vpp + 4);   // x0+1 ch4-7
        uint2 B2 = __ldg(vpp + 5);   // x0+1 ch8-11

        float w0 = wp[p] * wx0;
        float w1 = wp[p] * wx1;

        float2 a, b;
        a = u2f2(A0.x); b = u2f2(B0.x);
        acc[0]  = fmaf(w0, a.x, fmaf(w1, b.x, acc[0]));
        acc[1]  = fmaf(w0, a.y, fmaf(w1, b.y, acc[1]));
        a = u2f2(A0.y); b = u2f2(B0.y);
        acc[2]  = fmaf(w0, a.x, fmaf(w1, b.x, acc[2]));
        acc[3]  = fmaf(w0, a.y, fmaf(w1, b.y, acc[3]));
        a = u2f2(A1.x); b = u2f2(B1.x);
        acc[4]  = fmaf(w0, a.x, fmaf(w1, b.x, acc[4]));
        acc[5]  = fmaf(w0, a.y, fmaf(w1, b.y, acc[5]));
        a = u2f2(A1.y); b = u2f2(B1.y);
        acc[6]  = fmaf(w0, a.x, fmaf(w1, b.x, acc[6]));
        acc[7]  = fmaf(w0, a.y, fmaf(w1, b.y, acc[7]));
        a = u2f2(A2.x); b = u2f2(B2.x);
        acc[8]  = fmaf(w0, a.x, fmaf(w1, b.x, acc[8]));
        acc[9]  = fmaf(w0, a.y, fmaf(w1, b.y, acc[9]));
        a = u2f2(A2.y); b = u2f2(B2.y);
        acc[10] = fmaf(w0, a.x, fmaf(w1, b.x, acc[10]));
        acc[11] = fmaf(w0, a.y, fmaf(w1, b.y, acc[11]));
    }

    // out is [N, 12] row-major; 48B per thread -> 3x float4 streaming stores
    float4* o = reinterpret_cast<float4*>(out + (size_t)i * NCH);
    __stcs(o + 0, make_float4(acc[0], acc[1], acc[2],  acc[3]));
    __stcs(o + 1, make_float4(acc[4], acc[5], acc[6],  acc[7]));
    __stcs(o + 2, make_float4(acc[8], acc[9], acc[10], acc[11]));
}

extern "C" void kernel_launch(void* const* d_in, const int* in_sizes, int n_in,
                              void* d_out, int out_size) {
    const float* xyz     = (const float*)d_in[0];  // [N, 3]
    const float* grid    = (const float*)d_in[1];  // [1, 12, 160, 160, 160]
    const float* xyz_min = (const float*)d_in[2];  // [3]
    const float* xyz_max = (const float*)d_in[3];  // [3]
    float* out = (float*)d_out;                    // [N, 12]

    int n = in_sizes[0] / 3;

    {
        int threads = 256;
        int nthreads_total = GVOL / 2;               // 2 voxels per thread (GVOL even)
        int blocks = (nthreads_total + threads - 1) / threads;
        convert_cl_kernel<<<blocks, threads>>>(grid);
    }
    {
        int threads = 256;
        int blocks = (n + threads - 1) / threads;
        trilinear_sample_kernel<<<blocks, threads>>>(xyz, xyz_min, xyz_max, out, n);
    }
}

// round 10
// speedup vs baseline: 1.2329x; 1.0591x over previous
#include <cuda_runtime.h>
#include <cuda_fp16.h>
#include <cstdint>

// Problem constants (fixed by the dataset)
#define NCH   12
#define GD    160
#define GH    160
#define GW    160
#define GVOL  (GD * GH * GW)          // 4,096,000 voxels

// Interleaved channel-last fp16 grid: [D*H*W, 12] halfs = 24 B/voxel, 98.3 MB.
// +pad voxels: (a) the unconditional (x0+1) read at the last voxel (weight
// fx == 0 there), (b) the 64B aligned-window gather may over-read up to 16B
// past the pair. Padding is zero-initialized .bss.
__device__ __align__(16) __half g_grid_h[((size_t)GVOL + 8) * NCH];

// ---------------------------------------------------------------------------
// Pass 1: transpose+convert [C, D, H, W] fp32 -> [D*H*W, C] fp16.
// One thread = TWO consecutive voxels: 12x coalesced LDG.64 (float2) reads,
// 48 contiguous bytes out = 3x STG.128. fp32 reads stream (evict-first).
// ---------------------------------------------------------------------------
__global__ void __launch_bounds__(256) convert_cl_kernel(const float* __restrict__ grid) {
    int t = blockIdx.x * blockDim.x + threadIdx.x;
    int v = t * 2;
    if (v >= GVOL) return;

    __half h[2 * NCH];
#pragma unroll
    for (int c = 0; c < NCH; c++) {
        float2 f = __ldcs(reinterpret_cast<const float2*>(grid + (size_t)c * GVOL + v));
        h[c]       = __float2half(f.x);
        h[NCH + c] = __float2half(f.y);
    }

    uint4* dst = reinterpret_cast<uint4*>(g_grid_h + (size_t)v * NCH);
    const uint4* s = reinterpret_cast<const uint4*>(h);
    dst[0] = s[0];
    dst[1] = s[1];
    dst[2] = s[2];
}

// ---------------------------------------------------------------------------
// Pass 2: trilinear sample, one thread per point, all 12 channels.
// Each corner-pair (48B at 8B alignment) is fetched via a 16B-aligned 64B
// window: 4x LDG.128 -> 16 gather instructions/pt instead of 24. For a fully
// divergent gather the L1 wavefront cost is per-INSTRUCTION, so this cuts
// the L1tex wall ~1.5x. The 12 useful uint32s are selected from the window
// by a compile-time-unrolled SEL on the 0/8-byte misalignment.
// ---------------------------------------------------------------------------
__device__ __forceinline__ float2 u2f2(unsigned u) {
    __half2 h = *reinterpret_cast<__half2*>(&u);
    return __half22float2(h);
}

__global__ void __launch_bounds__(256, 4) trilinear_sample_kernel(
    const float* __restrict__ xyz,
    const float* __restrict__ xyz_min,
    const float* __restrict__ xyz_max,
    float* __restrict__ out,
    int n)
{
    int i = blockIdx.x * blockDim.x + threadIdx.x;
    if (i >= n) return;

    float p0 = __ldcs(xyz + 3 * (size_t)i + 0);
    float p1 = __ldcs(xyz + 3 * (size_t)i + 1);
    float p2 = __ldcs(xyz + 3 * (size_t)i + 2);

    float mn0 = __ldg(xyz_min + 0), mn1 = __ldg(xyz_min + 1), mn2 = __ldg(xyz_min + 2);
    float mx0 = __ldg(xyz_max + 0), mx1 = __ldg(xyz_max + 1), mx2 = __ldg(xyz_max + 2);

    float u0 = (p0 - mn0) / (mx0 - mn0);
    float u1 = (p1 - mn1) / (mx1 - mn1);
    float u2 = (p2 - mn2) / (mx2 - mn2);

    // px indexes W (from u2), py indexes H (from u1), pz indexes D (from u0)
    float px = u2 * (float)(GW - 1);
    float py = u1 * (float)(GH - 1);
    float pz = u0 * (float)(GD - 1);

    float xf = floorf(px), yf = floorf(py), zf = floorf(pz);
    float fx = px - xf,    fy = py - yf,    fz = pz - zf;

    int x0 = min(max((int)xf, 0), GW - 1);
    int y0 = min(max((int)yf, 0), GH - 1);
    int z0 = min(max((int)zf, 0), GD - 1);
    int y1 = min(y0 + 1, GH - 1);
    int z1 = min(z0 + 1, GD - 1);

    float wx0 = 1.0f - fx, wx1 = fx;
    float wy0 = 1.0f - fy, wy1 = fy;
    float wz0 = 1.0f - fz, wz1 = fz;

    float wp[4];
    wp[0] = wz0 * wy0;
    wp[1] = wz0 * wy1;
    wp[2] = wz1 * wy0;
    wp[3] = wz1 * wy1;

    int vidx[4];
    vidx[0] = (z0 * GH + y0) * GW + x0;
    vidx[1] = (z0 * GH + y1) * GW + x0;
    vidx[2] = (z1 * GH + y0) * GW + x0;
    vidx[3] = (z1 * GH + y1) * GW + x0;

    const char* gbase = reinterpret_cast<const char*>(g_grid_h);

    float acc[NCH];
#pragma unroll
    for (int c = 0; c < NCH; c++) acc[c] = 0.0f;

    // Two pairs in flight: 8x LDG.128 issued back-to-back, then consume.
#pragma unroll
    for (int pb = 0; pb < 4; pb += 2) {
        uint4 W[8];
        bool  sh[2];
#pragma unroll
        for (int t = 0; t < 2; t++) {
            int B = vidx[pb + t] * 24;           // byte offset; B mod 16 in {0,8}
            const uint4* q = reinterpret_cast<const uint4*>(gbase + (B & ~15));
            sh[t] = (B & 8) != 0;
            W[t * 4 + 0] = __ldg(q + 0);
            W[t * 4 + 1] = __ldg(q + 1);
            W[t * 4 + 2] = __ldg(q + 2);
            W[t * 4 + 3] = __ldg(q + 3);
        }

#pragma unroll
        for (int t = 0; t < 2; t++) {
            int p = pb + t;
            float w0 = wp[p] * wx0;
            float w1 = wp[p] * wx1;

            unsigned wd[16];
            wd[0]  = W[t*4+0].x; wd[1]  = W[t*4+0].y; wd[2]  = W[t*4+0].z; wd[3]  = W[t*4+0].w;
            wd[4]  = W[t*4+1].x; wd[5]  = W[t*4+1].y; wd[6]  = W[t*4+1].z; wd[7]  = W[t*4+1].w;
            wd[8]  = W[t*4+2].x; wd[9]  = W[t*4+2].y; wd[10] = W[t*4+2].z; wd[11] = W[t*4+2].w;
            wd[12] = W[t*4+3].x; wd[13] = W[t*4+3].y; wd[14] = W[t*4+3].z; wd[15] = W[t*4+3].w;

            // Select the 12 useful words: pair occupies wd[off .. off+11], off = sh?2:0
            unsigned u[12];
#pragma unroll
            for (int k = 0; k < 12; k++)
                u[k] = sh[t] ? wd[k + 2] : wd[k];

            // u[0..5] = x0 ch0-11 (half2 each), u[6..11] = x0+1 ch0-11
#pragma unroll
            for (int j = 0; j < 6; j++) {
                float2 a = u2f2(u[j]);
                float2 b = u2f2(u[6 + j]);
                acc[2*j]   = fmaf(w0, a.x, fmaf(w1, b.x, acc[2*j]));
                acc[2*j+1] = fmaf(w0, a.y, fmaf(w1, b.y, acc[2*j+1]));
            }
        }
    }

    // out is [N, 12] row-major; 48B per thread -> 3x float4 streaming stores
    float4* o = reinterpret_cast<float4*>(out + (size_t)i * NCH);
    __stcs(o + 0, make_float4(acc[0], acc[1], acc[2],  acc[3]));
    __stcs(o + 1, make_float4(acc[4], acc[5], acc[6],  acc[7]));
    __stcs(o + 2, make_float4(acc[8], acc[9], acc[10], acc[11]));
}

extern "C" void kernel_launch(void* const* d_in, const int* in_sizes, int n_in,
                              void* d_out, int out_size) {
    const float* xyz     = (const float*)d_in[0];  // [N, 3]
    const float* grid    = (const float*)d_in[1];  // [1, 12, 160, 160, 160]
    const float* xyz_min = (const float*)d_in[2];  // [3]
    const float* xyz_max = (const float*)d_in[3];  // [3]
    float* out = (float*)d_out;                    // [N, 12]

    int n = in_sizes[0] / 3;

    {
        int threads = 256;
        int nthreads_total = GVOL / 2;               // 2 voxels per thread (GVOL even)
        int blocks = (nthreads_total + threads - 1) / threads;
        convert_cl_kernel<<<blocks, threads>>>(grid);
    }
    {
        int threads = 256;
        int blocks = (n + threads - 1) / threads;
        trilinear_sample_kernel<<<blocks, threads>>>(xyz, xyz_min, xyz_max, out, n);
    }
}